// round 3
// baseline (speedup 1.0000x reference)
#include <cuda_runtime.h>
#include <math.h>

// Problem constants
#define NNODES   50000
#define DISTN    8
#define P_TOT    400000          // NNODES * DISTN
#define KCB      64
#define HIDN     256
#define NGRAPH   64
#define EPSV     0.1f
#define NITER    20
#define STABV    1e-8f
#define CLMAX    1e6f
#define BMARG    (1.0f/64.0f)

#define NBLK     (P_TOT / 32)    // 12500 fused blocks, 32 rows each
#define HBLK     98              // blocks that build the node histogram
#define HCHUNK   512             // nodes per hist block (98*512 >= 50000)

// Prune threshold: exp(-cost/EPS) == 0.0f (fp32, incl. subnormals) requires
// cost/EPS >= ~104. We prune only when the Cauchy-Schwarz lower bound
// (|x|_prefix - cmax)^2 >= 11  =>  true cost >= 11  =>  exp arg >= 110
// => exactly 0 in the reference as well (bit-exact pruning).
#define PRUNE_COST 11.0f

// Device scratch (__device__ globals only; no allocation)
__device__ float          g_Kmat[(size_t)P_TOT * KCB];  // valid only where flag=1
__device__ unsigned char  g_flag[P_TOT];
__device__ float          g_u[P_TOT];
__device__ float          g_ynorm[KCB];
__device__ int            g_nz[NGRAPH];                 // nonzero-row count per graph
__device__ int            g_hist[NGRAPH];               // nodes per graph
__device__ unsigned char  g_oz[64];                     // per-block "odd words all zero"
__device__ int            g_done;                       // ticket counter

// ---------------------------------------------------------------------------
// prep: codebook row norms (block b -> row b), int64-vs-int32 detection over
// the safe range (first NNODES 32-bit words, valid under both layouts),
// and scratch reset (g_nz, g_hist, g_done).
__global__ void __launch_bounds__(256) prep_kernel(const float* __restrict__ cb,
                                                   const int* __restrict__ b32) {
    const int b = blockIdx.x;      // 64 blocks
    const int t = threadIdx.x;     // 256 threads

    // ---- ynorm for codebook row b ----
    float v = cb[b * HIDN + t];
    float s = v * v;
    #pragma unroll
    for (int o = 16; o; o >>= 1) s += __shfl_xor_sync(~0u, s, o);
    __shared__ float red[8];
    if ((t & 31) == 0) red[t >> 5] = s;

    // ---- detection: if batch_idx is int64 (values < 2^31), every odd 32-bit
    // word of the first NNODES words is zero. Safe-range read only. ----
    int allz = 1;
    const int2* p2 = (const int2*)b32;
    for (int i = b * 256 + t; i < NNODES / 2; i += 64 * 256)
        if (p2[i].y != 0) allz = 0;
    allz = __all_sync(~0u, allz);
    __shared__ int oz[8];
    if ((t & 31) == 0) oz[t >> 5] = allz;
    __syncthreads();

    if (t == 0) {
        float yn = 0.f;
        #pragma unroll
        for (int i = 0; i < 8; i++) yn += red[i];
        g_ynorm[b] = yn;
        int o = 1;
        #pragma unroll
        for (int i = 0; i < 8; i++) o &= oz[i];
        g_oz[b] = (unsigned char)o;
        g_nz[b] = 0;
        g_hist[b] = 0;
        if (b == 0) g_done = 0;
    }
}

// ---------------------------------------------------------------------------
// fused: phase A = Kmat for 32 rows/block (4 rows per warp, two-stage
// prefix-norm pruning + rare exact fallback) and (blocks < HBLK) the node
// histogram. Phase B = atomic-ticket barrier; the last 64 tickets each run
// one graph's Sinkhorn (trivial when g_nz[b] == 0, which pruning guarantees
// is exact, not approximate).
__global__ void __launch_bounds__(256) fused_kernel(const float* __restrict__ x,
                                                    const float* __restrict__ cb,
                                                    const void* __restrict__ bidx,
                                                    float* __restrict__ out) {
    __shared__ float xs[8 * HIDN];
    __shared__ int   sh[NGRAPH];
    __shared__ float sV[64], sKTU[64], sW[64];
    __shared__ int   sRange[2];
    __shared__ float sTot;
    __shared__ int   sTicket;

    const int tid  = threadIdx.x;
    const int warp = tid >> 5;
    const int lane = tid & 31;
    const int oct  = lane >> 3;        // 4 rows per warp, 8 lanes per row
    const int ol   = lane & 7;
    const int row0 = (blockIdx.x * 8 + warp) * 4;
    const int row  = row0 + oct;

    // is64 from prep's per-block flags (64B, L2-hot)
    bool ozl = (g_oz[lane] != 0) && (g_oz[lane + 32] != 0);
    const int is64 = __all_sync(~0u, ozl);

    // cmax = max_k ||c_k||  (256B, L2-hot)
    float m = fmaxf(g_ynorm[lane], g_ynorm[lane + 32]);
    #pragma unroll
    for (int o = 16; o; o >>= 1) m = fmaxf(m, __shfl_xor_sync(~0u, m, o));
    const float cmax = sqrtf(m);

    const float4* xr = (const float4*)(x + (size_t)row * HIDN);

    // stage 1: floats [0,32) — one 128B line per row
    float4 a = xr[ol];
    float ps = a.x*a.x + a.y*a.y + a.z*a.z + a.w*a.w;
    ps += __shfl_xor_sync(~0u, ps, 4);
    ps += __shfl_xor_sync(~0u, ps, 2);
    ps += __shfl_xor_sync(~0u, ps, 1);
    float d = sqrtf(ps) - cmax;
    bool prune = (d > 0.f) && (d * d >= PRUNE_COST);

    // stage 2: floats [32,64) — only for rows not yet proven
    unsigned need2 = __ballot_sync(~0u, !prune);
    if (need2) {
        const bool mine = !prune;
        float4 bb = make_float4(0.f, 0.f, 0.f, 0.f);
        if (mine) bb = xr[8 + ol];
        float p2 = bb.x*bb.x + bb.y*bb.y + bb.z*bb.z + bb.w*bb.w;
        p2 += __shfl_xor_sync(~0u, p2, 4);
        p2 += __shfl_xor_sync(~0u, p2, 2);
        p2 += __shfl_xor_sync(~0u, p2, 1);
        if (mine) {
            ps += p2;
            d = sqrtf(ps) - cmax;
            prune = (d > 0.f) && (d * d >= PRUNE_COST);
        }
    }

    if (prune && ol == 0) g_flag[row] = 0;

    unsigned needf = __ballot_sync(~0u, !prune);
    if (needf) {
        // -------- rare exact fallback (general correctness) --------
        float4* sm = (float4*)(xs + warp * HIDN);
        for (int o2 = 0; o2 < 4; o2++) {
            if (!((needf >> (o2 * 8)) & 1u)) continue;
            const int r = row0 + o2;
            const float4* xr4 = (const float4*)(x + (size_t)r * HIDN);
            float4 va = xr4[lane];
            float4 vb = xr4[32 + lane];
            float s = va.x*va.x + va.y*va.y + va.z*va.z + va.w*va.w
                    + vb.x*vb.x + vb.y*vb.y + vb.z*vb.z + vb.w*vb.w;
            #pragma unroll
            for (int o = 16; o; o >>= 1) s += __shfl_xor_sync(~0u, s, o);
            const float xn = s;

            sm[lane] = va;
            sm[32 + lane] = vb;
            __syncwarp();

            const int c0 = lane, c1 = lane + 32;
            const float4* cb0 = (const float4*)(cb + (size_t)c0 * HIDN);
            const float4* cb1 = (const float4*)(cb + (size_t)c1 * HIDN);
            float d0 = 0.f, d1 = 0.f;
            #pragma unroll 8
            for (int t = 0; t < HIDN / 4; t++) {
                float4 xv = sm[t];
                float4 p = cb0[t], q = cb1[t];
                d0 += xv.x*p.x + xv.y*p.y + xv.z*p.z + xv.w*p.w;
                d1 += xv.x*q.x + xv.y*q.y + xv.z*q.z + xv.w*q.w;
            }
            float cost0 = xn + g_ynorm[c0] - 2.f * d0;
            float cost1 = xn + g_ynorm[c1] - 2.f * d1;

            // reference semantics: nan/inf cost -> Kmat = STAB (exp(-inf)=0 stays 0)
            float k0, k1;
            unsigned bits0 = __float_as_uint(cost0) & 0x7fffffffu;
            unsigned bits1 = __float_as_uint(cost1) & 0x7fffffffu;
            if (bits0 > 0x7f800000u) k0 = STABV;
            else                     k0 = expf(-fmaxf(cost0, 0.f) / EPSV);
            if (bits1 > 0x7f800000u) k1 = STABV;
            else                     k1 = expf(-fmaxf(cost1, 0.f) / EPSV);

            g_Kmat[(size_t)r * KCB + c0] = k0;
            g_Kmat[(size_t)r * KCB + c1] = k1;

            unsigned nz = __ballot_sync(~0u, (k0 != 0.f) || (k1 != 0.f));
            if (lane == 0) {
                g_flag[r] = nz ? 1 : 0;
                if (nz) {
                    const int node = r >> 3;
                    int g = is64 ? (int)((const long long*)bidx)[node]
                                 : ((const int*)bidx)[node];
                    g = min(max(g, 0), NGRAPH - 1);
                    atomicAdd(&g_nz[g], 1);
                }
            }
            __syncwarp();
        }
    }

    // -------- node histogram (first HBLK blocks) --------
    if (blockIdx.x < HBLK) {
        if (tid < NGRAPH) sh[tid] = 0;
        __syncthreads();
        const long long* b64 = (const long long*)bidx;
        const int*       b32 = (const int*)bidx;
        const int n0 = blockIdx.x * HCHUNK;
        const int n1 = min(n0 + HCHUNK, NNODES);
        for (int i = n0 + tid; i < n1; i += 256) {
            int g = is64 ? (int)b64[i] : b32[i];
            g = min(max(g, 0), NGRAPH - 1);
            atomicAdd(&sh[g], 1);
        }
        __syncthreads();
        if (tid < NGRAPH && sh[tid]) atomicAdd(&g_hist[tid], sh[tid]);
    }

    // -------- ticket barrier --------
    __syncthreads();
    if (tid == 0) {
        __threadfence();
        sTicket = atomicAdd(&g_done, 1);
    }
    __syncthreads();
    const int ticket = sTicket;
    if (ticket < NBLK - NGRAPH) return;
    const int b = ticket - (NBLK - NGRAPH);   // this block owns graph b

    if (tid == 0) {
        while (atomicAdd(&g_done, 0) < NBLK) __nanosleep(64);
        __threadfence();
        int s = 0;
        for (int g = 0; g < b; g++) s += g_hist[g];
        sRange[0] = s * DISTN;
        sRange[1] = (s + g_hist[b]) * DISTN;
    }
    if (tid < 64) { sV[tid] = 1.f; sKTU[tid] = 0.f; sW[tid] = 0.f; }
    __syncthreads();

    const int rs = sRange[0], re = sRange[1];

    // Fast path: every K row of this graph is exactly zero (bit-exact prune).
    if (g_nz[b] == 0) {
        if (tid < 64) out[b * KCB + tid] = (re == rs) ? 0.f : BMARG;
        return;
    }

    // -------- general Sinkhorn path (8 warps) --------
    const float aa = 1.f / fmaxf((float)(re - rs), 1.f);

    for (int iter = 0; iter < NITER; iter++) {
        float v0 = sV[lane], v1 = sV[lane + 32];
        float ktu0 = 0.f, ktu1 = 0.f;
        for (int r = rs + warp; r < re; r += 8) {
            if (!g_flag[r]) continue;
            float k0 = g_Kmat[(size_t)r * KCB + lane];
            float k1 = g_Kmat[(size_t)r * KCB + 32 + lane];
            float kv = k0 * v0 + k1 * v1;
            #pragma unroll
            for (int o = 16; o; o >>= 1) kv += __shfl_xor_sync(~0u, kv, o);
            float u = aa / fmaxf(kv, STABV);
            if (iter == NITER - 1 && lane == 0) g_u[r] = u;
            ktu0 += k0 * u;
            ktu1 += k1 * u;
        }
        atomicAdd(&sKTU[lane], ktu0);
        atomicAdd(&sKTU[lane + 32], ktu1);
        __syncthreads();
        if (tid < 64) {
            sV[tid] = BMARG / fmaxf(sKTU[tid], STABV);
            sKTU[tid] = 0.f;
        }
        __syncthreads();
    }

    {
        float w0 = 0.f, w1 = 0.f;
        for (int r = rs + warp; r < re; r += 8) {
            if (!g_flag[r]) continue;
            float uc = fminf(fmaxf(g_u[r], STABV), CLMAX);
            float k0 = g_Kmat[(size_t)r * KCB + lane];
            float k1 = g_Kmat[(size_t)r * KCB + 32 + lane];
            w0 += k0 * uc;
            w1 += k1 * uc;
        }
        atomicAdd(&sW[lane], w0);
        atomicAdd(&sW[lane + 32], w1);
    }
    __syncthreads();
    if (tid < 64) {
        float vc = fminf(fmaxf(sV[tid], STABV), CLMAX);
        sW[tid] = sW[tid] * vc;
    }
    __syncthreads();
    if (tid < 32) {
        float t = sW[tid] + sW[tid + 32];
        #pragma unroll
        for (int o = 16; o; o >>= 1) t += __shfl_xor_sync(~0u, t, o);
        if (tid == 0) sTot = t;
    }
    __syncthreads();
    if (tid < 64) {
        float total = sTot;
        float val = (total > STABV) ? (sW[tid] / fmaxf(total, STABV)) : BMARG;
        out[b * KCB + tid] = ((re - rs) == 0) ? 0.f : val;
    }
}

// ---------------------------------------------------------------------------
extern "C" void kernel_launch(void* const* d_in, const int* in_sizes, int n_in,
                              void* d_out, int out_size) {
    const float* x    = (const float*)d_in[0];   // node_distributions [50000,8,256]
    const void*  bidx = d_in[1];                 // batch_idx [50000] int64 or int32
    const float* cb   = (const float*)d_in[2];   // codebook [64,256]
    float* out = (float*)d_out;                  // [64,64] float32

    prep_kernel<<<64, 256>>>(cb, (const int*)bidx);
    fused_kernel<<<NBLK, 256>>>(x, cb, bidx, out);
}

// round 4
// speedup vs baseline: 1.2847x; 1.2847x over previous
#include <cuda_runtime.h>
#include <math.h>

// Problem constants
#define NNODES   50000
#define DISTN    8
#define P_TOT    400000          // NNODES * DISTN
#define KCB      64
#define HIDN     256
#define NGRAPH   64
#define EPSV     0.1f
#define NITER    20
#define STABV    1e-8f
#define CLMAX    1e6f
#define BMARG    (1.0f/64.0f)

// Prune threshold: exp(-cost/EPS) == 0.0f (fp32, incl. subnormals) requires
// cost/EPS >= ~104. We prune only when the Cauchy-Schwarz lower bound
// (|x|_prefix - cmax)^2 >= 11  =>  true cost >= 11  =>  exp arg >= 110
// => exactly 0 in the reference as well (bit-exact pruning).
#define PRUNE_COST 11.0f

// Device scratch (__device__ globals only; no allocation)
__device__ float          g_Kmat[(size_t)P_TOT * KCB];  // valid only where flag=1
__device__ unsigned char  g_flag[P_TOT];
__device__ float          g_u[P_TOT];
__device__ float          g_ynorm[KCB];
__device__ int            g_cmax_bits;
__device__ int            g_nz[NGRAPH];                 // nonzero-row count per graph
__device__ int            g_hist[NGRAPH];               // nodes per graph
__device__ unsigned char  g_oz[64];                     // per-block "odd words all zero"

// ---------------------------------------------------------------------------
// prep: codebook row norms + cmax (block b -> codebook row b), int64-vs-int32
// detection (safe range: first NNODES 32-bit words exist under both layouts),
// node histogram, scratch reset.
__global__ void __launch_bounds__(256) prep_kernel(const float* __restrict__ cb,
                                                   const int* __restrict__ b32raw,
                                                   const void* __restrict__ bidx) {
    const int b = blockIdx.x;      // 64 blocks
    const int t = threadIdx.x;     // 256 threads

    __shared__ float red[8];
    __shared__ int   oz[8];
    __shared__ int   sh[NGRAPH];
    __shared__ int   sIs64;

    if (t == 0 && b == 0) g_cmax_bits = 0;   // benign race: all writers race to
                                             // set before use? No -> do atomic path below.
    if (t < NGRAPH) sh[t] = 0;

    // ---- ynorm for codebook row b ----
    float v = cb[b * HIDN + t];
    float s = v * v;
    #pragma unroll
    for (int o = 16; o; o >>= 1) s += __shfl_xor_sync(~0u, s, o);
    if ((t & 31) == 0) red[t >> 5] = s;

    // ---- int64 detection ----
    int allz = 1;
    const int2* p2 = (const int2*)b32raw;
    for (int i = b * 256 + t; i < NNODES / 2; i += 64 * 256)
        if (p2[i].y != 0) allz = 0;
    allz = __all_sync(~0u, allz);
    if ((t & 31) == 0) oz[t >> 5] = allz;
    __syncthreads();

    if (t == 0) {
        float yn = 0.f;
        #pragma unroll
        for (int i = 0; i < 8; i++) yn += red[i];
        g_ynorm[b] = yn;
        int o = 1;
        #pragma unroll
        for (int i = 0; i < 8; i++) o &= oz[i];
        g_oz[b] = (unsigned char)o;
        sIs64 = o;                 // conservative: this block's view; refined below
        g_nz[b] = 0;
        g_hist[b] = 0;             // reset before atomics below? ordering hazard ->
                                   // use separate accumulation buffer sh, flush once.
    }
    __syncthreads();

    // NOTE on g_hist reset ordering across blocks: block b resets g_hist[b];
    // any block may atomically add to g_hist[g] afterward. Both happen inside
    // this same kernel -> race. Fix: accumulate per-block into smem and flush
    // with atomicAdd; resets must complete first. Use a two-phase trick:
    // resets were done in a PREVIOUS kernel? We have none. Instead: each block
    // owns histogram chunk writes NON-atomically? Simplest safe route:
    // compute the full histogram redundantly in block b for its own bin only.
    {
        // Each block counts, over ALL nodes, how many land in bin b.
        // 400KB scan per block stays in L2 (64 blocks share it) ~ cheap.
        const int is64 = sIs64;   // per-block detection view is globally
                                  // consistent only if data is; both layouts
                                  // yield same result for counting bin b when
                                  // is64 matches the true layout. Use local
                                  // full detection: allz above covered a
                                  // 1/64 slice only -> recompute exact:
        // exact detection for this block (full safe range):
        int az = 1;
        for (int i = t; i < NNODES / 2; i += 256)
            if (p2[i].y != 0) az = 0;
        az = __all_sync(~0u, az);
        if ((t & 31) == 0) oz[t >> 5] = az;
        __syncthreads();
        int full_is64 = 1;
        #pragma unroll
        for (int i = 0; i < 8; i++) full_is64 &= oz[i];

        const long long* b64 = (const long long*)bidx;
        const int*       b32 = (const int*)bidx;
        int cnt = 0;
        for (int i = t; i < NNODES; i += 256) {
            int g = full_is64 ? (int)b64[i] : b32[i];
            if (g == b) cnt++;
        }
        #pragma unroll
        for (int o = 16; o; o >>= 1) cnt += __shfl_xor_sync(~0u, cnt, o);
        if ((t & 31) == 0) sh[t >> 5] = cnt;
        __syncthreads();
        if (t == 0) {
            int c = 0;
            #pragma unroll
            for (int i = 0; i < 8; i++) c += sh[i];
            g_hist[b] = c;   // sole writer of bin b: no race
            // cmax via atomicMax on IEEE bits (yn >= 0 -> monotonic)
            atomicMax(&g_cmax_bits, __float_as_int(sqrtf(g_ynorm[b])));
        }
    }
}

// ---------------------------------------------------------------------------
// kmat: ONE THREAD PER ROW. Stage 1 loads the row's first 32 floats as 8
// back-to-back LDG.128 (MLP=8), prunes via the prefix-norm bound. Stage 2
// (rare) reads floats [32,64). Fallback (rarer): warp-cooperative exact path.
__global__ void __launch_bounds__(256) kmat_kernel(const float* __restrict__ x,
                                                   const float* __restrict__ cb,
                                                   const void* __restrict__ bidx) {
    __shared__ float xs[8 * HIDN];
    const int tid  = threadIdx.x;
    const int warp = tid >> 5;
    const int lane = tid & 31;
    const int row  = blockIdx.x * 256 + tid;
    const bool valid = (row < P_TOT);

    const float cmax = __int_as_float(g_cmax_bits);

    const float4* xr = (const float4*)(x + (size_t)row * HIDN);

    // stage 1: floats [0,32) — 8 independent vector loads, front-batched
    float ps = 0.f;
    if (valid) {
        float4 r0 = xr[0], r1 = xr[1], r2 = xr[2], r3 = xr[3];
        float4 r4 = xr[4], r5 = xr[5], r6 = xr[6], r7 = xr[7];
        ps  = r0.x*r0.x + r0.y*r0.y + r0.z*r0.z + r0.w*r0.w;
        ps += r1.x*r1.x + r1.y*r1.y + r1.z*r1.z + r1.w*r1.w;
        ps += r2.x*r2.x + r2.y*r2.y + r2.z*r2.z + r2.w*r2.w;
        ps += r3.x*r3.x + r3.y*r3.y + r3.z*r3.z + r3.w*r3.w;
        ps += r4.x*r4.x + r4.y*r4.y + r4.z*r4.z + r4.w*r4.w;
        ps += r5.x*r5.x + r5.y*r5.y + r5.z*r5.z + r5.w*r5.w;
        ps += r6.x*r6.x + r6.y*r6.y + r6.z*r6.z + r6.w*r6.w;
        ps += r7.x*r7.x + r7.y*r7.y + r7.z*r7.z + r7.w*r7.w;
    }
    float d = sqrtf(ps) - cmax;
    bool prune = valid && (d > 0.f) && (d * d >= PRUNE_COST);

    // stage 2: floats [32,64) — only for rows not yet proven
    if (__ballot_sync(~0u, valid && !prune)) {
        if (valid && !prune) {
            float4 r0 = xr[8],  r1 = xr[9],  r2 = xr[10], r3 = xr[11];
            float4 r4 = xr[12], r5 = xr[13], r6 = xr[14], r7 = xr[15];
            ps += r0.x*r0.x + r0.y*r0.y + r0.z*r0.z + r0.w*r0.w;
            ps += r1.x*r1.x + r1.y*r1.y + r1.z*r1.z + r1.w*r1.w;
            ps += r2.x*r2.x + r2.y*r2.y + r2.z*r2.z + r2.w*r2.w;
            ps += r3.x*r3.x + r3.y*r3.y + r3.z*r3.z + r3.w*r3.w;
            ps += r4.x*r4.x + r4.y*r4.y + r4.z*r4.z + r4.w*r4.w;
            ps += r5.x*r5.x + r5.y*r5.y + r5.z*r5.z + r5.w*r5.w;
            ps += r6.x*r6.x + r6.y*r6.y + r6.z*r6.z + r6.w*r6.w;
            ps += r7.x*r7.x + r7.y*r7.y + r7.z*r7.z + r7.w*r7.w;
            d = sqrtf(ps) - cmax;
            prune = (d > 0.f) && (d * d >= PRUNE_COST);
        }
    }

    if (valid && prune) g_flag[row] = 0;

    // -------- rare exact fallback: warp processes failing rows jointly -----
    unsigned needf = __ballot_sync(~0u, valid && !prune);
    if (!needf) return;

    bool ozl = (g_oz[lane] != 0) && (g_oz[lane + 32] != 0);
    const int is64 = __all_sync(~0u, ozl);

    float4* sm = (float4*)(xs + warp * HIDN);
    while (needf) {
        const int src = __ffs(needf) - 1;
        needf &= needf - 1;
        const int r = blockIdx.x * 256 + warp * 32 + src;

        const float4* xr4 = (const float4*)(x + (size_t)r * HIDN);
        float4 va = xr4[lane];
        float4 vb = xr4[32 + lane];
        float s = va.x*va.x + va.y*va.y + va.z*va.z + va.w*va.w
                + vb.x*vb.x + vb.y*vb.y + vb.z*vb.z + vb.w*vb.w;
        #pragma unroll
        for (int o = 16; o; o >>= 1) s += __shfl_xor_sync(~0u, s, o);
        const float xn = s;

        sm[lane] = va;
        sm[32 + lane] = vb;
        __syncwarp();

        const int c0 = lane, c1 = lane + 32;
        const float4* cb0 = (const float4*)(cb + (size_t)c0 * HIDN);
        const float4* cb1 = (const float4*)(cb + (size_t)c1 * HIDN);
        float d0 = 0.f, d1 = 0.f;
        #pragma unroll 8
        for (int t = 0; t < HIDN / 4; t++) {
            float4 xv = sm[t];
            float4 p = cb0[t], q = cb1[t];
            d0 += xv.x*p.x + xv.y*p.y + xv.z*p.z + xv.w*p.w;
            d1 += xv.x*q.x + xv.y*q.y + xv.z*q.z + xv.w*q.w;
        }
        float cost0 = xn + g_ynorm[c0] - 2.f * d0;
        float cost1 = xn + g_ynorm[c1] - 2.f * d1;

        // reference semantics: nan/inf cost -> Kmat = STAB (exp(-inf)=0 stays 0)
        float k0, k1;
        unsigned bits0 = __float_as_uint(cost0) & 0x7fffffffu;
        unsigned bits1 = __float_as_uint(cost1) & 0x7fffffffu;
        if (bits0 > 0x7f800000u) k0 = STABV;
        else                     k0 = expf(-fmaxf(cost0, 0.f) / EPSV);
        if (bits1 > 0x7f800000u) k1 = STABV;
        else                     k1 = expf(-fmaxf(cost1, 0.f) / EPSV);

        g_Kmat[(size_t)r * KCB + c0] = k0;
        g_Kmat[(size_t)r * KCB + c1] = k1;

        unsigned nz = __ballot_sync(~0u, (k0 != 0.f) || (k1 != 0.f));
        if (lane == 0) {
            g_flag[r] = nz ? 1 : 0;
            if (nz) {
                const int node = r >> 3;
                int g = is64 ? (int)((const long long*)bidx)[node]
                             : ((const int*)bidx)[node];
                g = min(max(g, 0), NGRAPH - 1);
                atomicAdd(&g_nz[g], 1);
            }
        }
        __syncwarp();
    }
}

// ---------------------------------------------------------------------------
// sinkhorn: one block per graph; g_hist precomputed by prep. Fast path when
// the graph's K rows are all exactly zero (guaranteed exact by pruning).
__global__ void __launch_bounds__(256) sinkhorn_kernel(float* __restrict__ out) {
    __shared__ float sV[64], sKTU[64], sW[64];
    __shared__ int   sRange[2];
    __shared__ float sTot;

    const int b    = blockIdx.x;
    const int tid  = threadIdx.x;
    const int lane = tid & 31;
    const int warp = tid >> 5;        // 8 warps

    if (tid == 0) {
        int s = 0;
        for (int g = 0; g < b; g++) s += g_hist[g];
        sRange[0] = s * DISTN;
        sRange[1] = (s + g_hist[b]) * DISTN;
    }
    if (tid < 64) { sV[tid] = 1.f; sKTU[tid] = 0.f; sW[tid] = 0.f; }
    __syncthreads();

    const int rs = sRange[0], re = sRange[1];

    // Fast path: every K row of this graph is exactly zero.
    if (g_nz[b] == 0) {
        if (tid < 64) out[b * KCB + tid] = (re == rs) ? 0.f : BMARG;
        return;
    }

    // -------- general Sinkhorn path --------
    const float aa = 1.f / fmaxf((float)(re - rs), 1.f);

    for (int iter = 0; iter < NITER; iter++) {
        float v0 = sV[lane], v1 = sV[lane + 32];
        float ktu0 = 0.f, ktu1 = 0.f;
        for (int r = rs + warp; r < re; r += 8) {
            if (!g_flag[r]) continue;
            float k0 = g_Kmat[(size_t)r * KCB + lane];
            float k1 = g_Kmat[(size_t)r * KCB + 32 + lane];
            float kv = k0 * v0 + k1 * v1;
            #pragma unroll
            for (int o = 16; o; o >>= 1) kv += __shfl_xor_sync(~0u, kv, o);
            float u = aa / fmaxf(kv, STABV);
            if (iter == NITER - 1 && lane == 0) g_u[r] = u;
            ktu0 += k0 * u;
            ktu1 += k1 * u;
        }
        atomicAdd(&sKTU[lane], ktu0);
        atomicAdd(&sKTU[lane + 32], ktu1);
        __syncthreads();
        if (tid < 64) {
            sV[tid] = BMARG / fmaxf(sKTU[tid], STABV);
            sKTU[tid] = 0.f;
        }
        __syncthreads();
    }

    {
        float w0 = 0.f, w1 = 0.f;
        for (int r = rs + warp; r < re; r += 8) {
            if (!g_flag[r]) continue;
            float uc = fminf(fmaxf(g_u[r], STABV), CLMAX);
            float k0 = g_Kmat[(size_t)r * KCB + lane];
            float k1 = g_Kmat[(size_t)r * KCB + 32 + lane];
            w0 += k0 * uc;
            w1 += k1 * uc;
        }
        atomicAdd(&sW[lane], w0);
        atomicAdd(&sW[lane + 32], w1);
    }
    __syncthreads();
    if (tid < 64) {
        float vc = fminf(fmaxf(sV[tid], STABV), CLMAX);
        sW[tid] = sW[tid] * vc;
    }
    __syncthreads();
    if (tid < 32) {
        float t = sW[tid] + sW[tid + 32];
        #pragma unroll
        for (int o = 16; o; o >>= 1) t += __shfl_xor_sync(~0u, t, o);
        if (tid == 0) sTot = t;
    }
    __syncthreads();
    if (tid < 64) {
        float total = sTot;
        float val = (total > STABV) ? (sW[tid] / fmaxf(total, STABV)) : BMARG;
        out[b * KCB + tid] = ((re - rs) == 0) ? 0.f : val;
    }
}

// ---------------------------------------------------------------------------
extern "C" void kernel_launch(void* const* d_in, const int* in_sizes, int n_in,
                              void* d_out, int out_size) {
    const float* x    = (const float*)d_in[0];   // node_distributions [50000,8,256]
    const void*  bidx = d_in[1];                 // batch_idx [50000] int64 or int32
    const float* cb   = (const float*)d_in[2];   // codebook [64,256]
    float* out = (float*)d_out;                  // [64,64] float32

    prep_kernel<<<64, 256>>>(cb, (const int*)bidx, bidx);
    kmat_kernel<<<(P_TOT + 255) / 256, 256>>>(x, cb, bidx);
    sinkhorn_kernel<<<NGRAPH, 256>>>(out);
}

// round 5
// speedup vs baseline: 2.3571x; 1.8348x over previous
#include <cuda_runtime.h>
#include <math.h>

// Problem constants
#define NNODES   50000
#define DISTN    8
#define P_TOT    400000          // NNODES * DISTN
#define KCB      64
#define HIDN     256
#define NGRAPH   64
#define EPSV     0.1f
#define NITER    20
#define STABV    1e-8f
#define CLMAX    1e6f
#define BMARG    (1.0f/64.0f)

#define NBLK     ((P_TOT + 255) / 256)   // 1563 kmat blocks, 256 rows each
#define HBLK     98                      // kmat blocks that also build the histogram
#define HCHUNK   512                     // nodes per hist block (98*512 >= 50000)

// Prune threshold: exp(-cost/EPS) == 0.0f (fp32, incl. subnormals) requires
// cost/EPS >= ~104. We prune only when the Cauchy-Schwarz lower bound
// (|x|_prefix - cmax)^2 >= 11  =>  true cost >= 11  =>  exp arg >= 110
// => exactly 0 in the reference as well (bit-exact pruning).
#define PRUNE_COST 11.0f

// Device scratch (__device__ globals only; no allocation)
__device__ float          g_Kmat[(size_t)P_TOT * KCB];  // valid only where flag=1
__device__ unsigned char  g_flag[P_TOT];
__device__ float          g_u[P_TOT];
__device__ float          g_ynorm[KCB];
__device__ int            g_nz[NGRAPH];                 // nonzero-row count per graph
__device__ int            g_hist[NGRAPH];               // nodes per graph
__device__ unsigned char  g_oz[64];                     // per-block "odd words all zero"

// ---------------------------------------------------------------------------
// prep: codebook row norm for row b (block b), 1/64 slice of int64-vs-int32
// detection (safe range: first NNODES 32-bit words exist under both layouts),
// and zeroing of g_nz / g_hist (consumed by the NEXT kernel -> no race).
__global__ void __launch_bounds__(256) prep_kernel(const float* __restrict__ cb,
                                                   const int* __restrict__ b32raw) {
    const int b = blockIdx.x;      // 64 blocks
    const int t = threadIdx.x;     // 256 threads

    __shared__ float red[8];
    __shared__ int   oz[8];

    // ---- ynorm for codebook row b ----
    float v = cb[b * HIDN + t];
    float s = v * v;
    #pragma unroll
    for (int o = 16; o; o >>= 1) s += __shfl_xor_sync(~0u, s, o);
    if ((t & 31) == 0) red[t >> 5] = s;

    // ---- detection slice: odd 32-bit words all zero <=> int64 layout ----
    int allz = 1;
    const int2* p2 = (const int2*)b32raw;
    for (int i = b * 256 + t; i < NNODES / 2; i += 64 * 256)
        if (p2[i].y != 0) allz = 0;
    allz = __all_sync(~0u, allz);
    if ((t & 31) == 0) oz[t >> 5] = allz;
    __syncthreads();

    if (t == 0) {
        float yn = 0.f;
        #pragma unroll
        for (int i = 0; i < 8; i++) yn += red[i];
        g_ynorm[b] = yn;
        int o = 1;
        #pragma unroll
        for (int i = 0; i < 8; i++) o &= oz[i];
        g_oz[b] = (unsigned char)o;
        g_nz[b] = 0;
        g_hist[b] = 0;
    }
}

// ---------------------------------------------------------------------------
// kmat: one warp = 32 rows. Lane (oct,ol) reads float4 #ol of row (4g+oct):
// 8 independent, fully-coalesced LDG.128 (4 lines each, MLP=8, 1 wavefront
// per row). Prefix-norm prune (bit-exact); rare stage-2; rarer exact fallback.
// Blocks < HBLK additionally build the per-graph node histogram.
__global__ void __launch_bounds__(256) kmat_kernel(const float* __restrict__ x,
                                                   const float* __restrict__ cb,
                                                   const void* __restrict__ bidx) {
    __shared__ float xs[8 * HIDN];
    __shared__ int   sh[NGRAPH];

    const int tid  = threadIdx.x;
    const int warp = tid >> 5;
    const int lane = tid & 31;
    const int oct  = lane >> 3;        // 4 rows per load group
    const int ol   = lane & 7;         // 8 lanes per row (8 x 16B = 128B line)
    const int r0   = (blockIdx.x * 8 + warp) * 32;

    // is64 (AND of per-slice detection flags; 64B, L2-hot)
    bool ozl = (g_oz[lane] != 0) && (g_oz[lane + 32] != 0);
    const int is64 = __all_sync(~0u, ozl);

    // cmax = max_k ||c_k||  (256B, L2-hot)
    float m = fmaxf(g_ynorm[lane], g_ynorm[lane + 32]);
    #pragma unroll
    for (int o = 16; o; o >>= 1) m = fmaxf(m, __shfl_xor_sync(~0u, m, o));
    const float cmax = sqrtf(m);

    // ---- stage 1: front-batched loads of floats [0,32) of 32 rows ----
    float4 v[8];
    #pragma unroll
    for (int g = 0; g < 8; g++) {
        const int r = r0 + g * 4 + oct;
        v[g] = make_float4(0.f, 0.f, 0.f, 0.f);
        if (r < P_TOT)
            v[g] = ((const float4*)(x + (size_t)r * HIDN))[ol];
    }
    float ps[8];
    bool  pr[8];
    #pragma unroll
    for (int g = 0; g < 8; g++) {
        float p = v[g].x*v[g].x + v[g].y*v[g].y + v[g].z*v[g].z + v[g].w*v[g].w;
        p += __shfl_xor_sync(~0u, p, 4);
        p += __shfl_xor_sync(~0u, p, 2);
        p += __shfl_xor_sync(~0u, p, 1);
        ps[g] = p;
        float d = sqrtf(p) - cmax;
        const int r = r0 + g * 4 + oct;
        pr[g] = (r >= P_TOT) || ((d > 0.f) && (d * d >= PRUNE_COST));
    }

    bool allp = pr[0] && pr[1] && pr[2] && pr[3] && pr[4] && pr[5] && pr[6] && pr[7];
    unsigned anyb = __ballot_sync(~0u, !allp);

    // ---- stage 2: floats [32,64) only for rows not yet proven ----
    if (anyb) {
        float4 v2[8];
        #pragma unroll
        for (int g = 0; g < 8; g++) {
            v2[g] = make_float4(0.f, 0.f, 0.f, 0.f);
            const int r = r0 + g * 4 + oct;
            if (!pr[g] && r < P_TOT)
                v2[g] = ((const float4*)(x + (size_t)r * HIDN))[8 + ol];
        }
        #pragma unroll
        for (int g = 0; g < 8; g++) {
            float p = v2[g].x*v2[g].x + v2[g].y*v2[g].y + v2[g].z*v2[g].z + v2[g].w*v2[g].w;
            p += __shfl_xor_sync(~0u, p, 4);
            p += __shfl_xor_sync(~0u, p, 2);
            p += __shfl_xor_sync(~0u, p, 1);
            ps[g] += p;
            const int r = r0 + g * 4 + oct;
            if (!pr[g]) {
                float d = sqrtf(ps[g]) - cmax;
                pr[g] = (r >= P_TOT) || ((d > 0.f) && (d * d >= PRUNE_COST));
            }
        }
        allp = pr[0] && pr[1] && pr[2] && pr[3] && pr[4] && pr[5] && pr[6] && pr[7];
        anyb = __ballot_sync(~0u, !allp);
    }

    // ---- bulk-zero this warp's 32 flag bytes (fallback overwrites its rows) ----
    if (r0 + 32 <= P_TOT) {
        if (lane < 8) ((unsigned*)(g_flag + r0))[lane] = 0u;
    } else {
        for (int i = lane; r0 + i < P_TOT; i += 32) g_flag[r0 + i] = 0;
    }
    __syncwarp();

    // ---- rare exact fallback ----
    if (anyb) {
        // row bitmask: bit (g*4+oct) = row r0+g*4+oct unproven
        unsigned needf = 0;
        #pragma unroll
        for (int g = 0; g < 8; g++) {
            unsigned bg = __ballot_sync(~0u, !pr[g]);
            needf |= ((bg       & 1u) << (g * 4 + 0))
                   | (((bg >> 8)  & 1u) << (g * 4 + 1))
                   | (((bg >> 16) & 1u) << (g * 4 + 2))
                   | (((bg >> 24) & 1u) << (g * 4 + 3));
        }

        float4* sm = (float4*)(xs + warp * HIDN);
        while (needf) {
            const int idx = __ffs(needf) - 1;
            needf &= needf - 1;
            const int r = r0 + idx;

            const float4* xr4 = (const float4*)(x + (size_t)r * HIDN);
            float4 va = xr4[lane];
            float4 vb = xr4[32 + lane];
            float s = va.x*va.x + va.y*va.y + va.z*va.z + va.w*va.w
                    + vb.x*vb.x + vb.y*vb.y + vb.z*vb.z + vb.w*vb.w;
            #pragma unroll
            for (int o = 16; o; o >>= 1) s += __shfl_xor_sync(~0u, s, o);
            const float xn = s;

            sm[lane] = va;
            sm[32 + lane] = vb;
            __syncwarp();

            const int c0 = lane, c1 = lane + 32;
            const float4* cb0 = (const float4*)(cb + (size_t)c0 * HIDN);
            const float4* cb1 = (const float4*)(cb + (size_t)c1 * HIDN);
            float d0 = 0.f, d1 = 0.f;
            #pragma unroll 8
            for (int t = 0; t < HIDN / 4; t++) {
                float4 xv = sm[t];
                float4 p = cb0[t], q = cb1[t];
                d0 += xv.x*p.x + xv.y*p.y + xv.z*p.z + xv.w*p.w;
                d1 += xv.x*q.x + xv.y*q.y + xv.z*q.z + xv.w*q.w;
            }
            float cost0 = xn + g_ynorm[c0] - 2.f * d0;
            float cost1 = xn + g_ynorm[c1] - 2.f * d1;

            // reference semantics: nan/inf cost -> Kmat = STAB (exp(-inf)=0 stays 0)
            float k0, k1;
            unsigned bits0 = __float_as_uint(cost0) & 0x7fffffffu;
            unsigned bits1 = __float_as_uint(cost1) & 0x7fffffffu;
            if (bits0 > 0x7f800000u) k0 = STABV;
            else                     k0 = expf(-fmaxf(cost0, 0.f) / EPSV);
            if (bits1 > 0x7f800000u) k1 = STABV;
            else                     k1 = expf(-fmaxf(cost1, 0.f) / EPSV);

            g_Kmat[(size_t)r * KCB + c0] = k0;
            g_Kmat[(size_t)r * KCB + c1] = k1;

            unsigned nz = __ballot_sync(~0u, (k0 != 0.f) || (k1 != 0.f));
            if (lane == 0) {
                g_flag[r] = nz ? 1 : 0;
                if (nz) {
                    const int node = r >> 3;
                    int g = is64 ? (int)((const long long*)bidx)[node]
                                 : ((const int*)bidx)[node];
                    g = min(max(g, 0), NGRAPH - 1);
                    atomicAdd(&g_nz[g], 1);
                }
            }
            __syncwarp();
        }
    }

    // ---- per-graph node histogram (first HBLK blocks; g_hist zeroed by prep) ----
    if (blockIdx.x < HBLK) {
        if (tid < NGRAPH) sh[tid] = 0;
        __syncthreads();
        const long long* b64 = (const long long*)bidx;
        const int*       b32 = (const int*)bidx;
        const int n0 = blockIdx.x * HCHUNK;
        const int n1 = min(n0 + HCHUNK, NNODES);
        for (int i = n0 + tid; i < n1; i += 256) {
            int g = is64 ? (int)b64[i] : b32[i];
            g = min(max(g, 0), NGRAPH - 1);
            atomicAdd(&sh[g], 1);
        }
        __syncthreads();
        if (tid < NGRAPH && sh[tid]) atomicAdd(&g_hist[tid], sh[tid]);
    }
}

// ---------------------------------------------------------------------------
// sinkhorn: one block per graph; g_hist precomputed. Fast path when the
// graph's K rows are all exactly zero (guaranteed exact by pruning).
__global__ void __launch_bounds__(256) sinkhorn_kernel(float* __restrict__ out) {
    __shared__ float sV[64], sKTU[64], sW[64];
    __shared__ int   sRange[2];
    __shared__ float sTot;

    const int b    = blockIdx.x;
    const int tid  = threadIdx.x;
    const int lane = tid & 31;
    const int warp = tid >> 5;        // 8 warps

    if (tid == 0) {
        int s = 0;
        for (int g = 0; g < b; g++) s += g_hist[g];
        sRange[0] = s * DISTN;
        sRange[1] = (s + g_hist[b]) * DISTN;
    }
    if (tid < 64) { sV[tid] = 1.f; sKTU[tid] = 0.f; sW[tid] = 0.f; }
    __syncthreads();

    const int rs = sRange[0], re = sRange[1];

    // Fast path: every K row of this graph is exactly zero.
    if (g_nz[b] == 0) {
        if (tid < 64) out[b * KCB + tid] = (re == rs) ? 0.f : BMARG;
        return;
    }

    // -------- general Sinkhorn path --------
    const float aa = 1.f / fmaxf((float)(re - rs), 1.f);

    for (int iter = 0; iter < NITER; iter++) {
        float v0 = sV[lane], v1 = sV[lane + 32];
        float ktu0 = 0.f, ktu1 = 0.f;
        for (int r = rs + warp; r < re; r += 8) {
            if (!g_flag[r]) continue;
            float k0 = g_Kmat[(size_t)r * KCB + lane];
            float k1 = g_Kmat[(size_t)r * KCB + 32 + lane];
            float kv = k0 * v0 + k1 * v1;
            #pragma unroll
            for (int o = 16; o; o >>= 1) kv += __shfl_xor_sync(~0u, kv, o);
            float u = aa / fmaxf(kv, STABV);
            if (iter == NITER - 1 && lane == 0) g_u[r] = u;
            ktu0 += k0 * u;
            ktu1 += k1 * u;
        }
        atomicAdd(&sKTU[lane], ktu0);
        atomicAdd(&sKTU[lane + 32], ktu1);
        __syncthreads();
        if (tid < 64) {
            sV[tid] = BMARG / fmaxf(sKTU[tid], STABV);
            sKTU[tid] = 0.f;
        }
        __syncthreads();
    }

    {
        float w0 = 0.f, w1 = 0.f;
        for (int r = rs + warp; r < re; r += 8) {
            if (!g_flag[r]) continue;
            float uc = fminf(fmaxf(g_u[r], STABV), CLMAX);
            float k0 = g_Kmat[(size_t)r * KCB + lane];
            float k1 = g_Kmat[(size_t)r * KCB + 32 + lane];
            w0 += k0 * uc;
            w1 += k1 * uc;
        }
        atomicAdd(&sW[lane], w0);
        atomicAdd(&sW[lane + 32], w1);
    }
    __syncthreads();
    if (tid < 64) {
        float vc = fminf(fmaxf(sV[tid], STABV), CLMAX);
        sW[tid] = sW[tid] * vc;
    }
    __syncthreads();
    if (tid < 32) {
        float t = sW[tid] + sW[tid + 32];
        #pragma unroll
        for (int o = 16; o; o >>= 1) t += __shfl_xor_sync(~0u, t, o);
        if (tid == 0) sTot = t;
    }
    __syncthreads();
    if (tid < 64) {
        float total = sTot;
        float val = (total > STABV) ? (sW[tid] / fmaxf(total, STABV)) : BMARG;
        out[b * KCB + tid] = ((re - rs) == 0) ? 0.f : val;
    }
}

// ---------------------------------------------------------------------------
extern "C" void kernel_launch(void* const* d_in, const int* in_sizes, int n_in,
                              void* d_out, int out_size) {
    const float* x    = (const float*)d_in[0];   // node_distributions [50000,8,256]
    const void*  bidx = d_in[1];                 // batch_idx [50000] int64 or int32
    const float* cb   = (const float*)d_in[2];   // codebook [64,256]
    float* out = (float*)d_out;                  // [64,64] float32

    prep_kernel<<<64, 256>>>(cb, (const int*)bidx);
    kmat_kernel<<<NBLK, 256>>>(x, cb, bidx);
    sinkhorn_kernel<<<NGRAPH, 256>>>(out);
}